// round 11
// baseline (speedup 1.0000x reference)
#include <cuda_runtime.h>
#include <cfloat>
#include <cstdint>

#define NCB 8
#define KCB 1024
#define DIM 128
#define NROWS 32768
#define MTILE 128
#define NCTA (NROWS/MTILE)     // 256
#define NTHR 128
#define CH 64
#define NCHUNK 16
#define TOTCH (NCB*NCHUNK)      // 128
#define RSTR (DIM+4)

#define CODES_ELEMS (NROWS*NCB)
#define Q_ELEMS     (NROWS*DIM)

#define TM_A 256                 // A: cols 256..383 ; D ring: 4 x 64 cols at 0,64,128,192

#define MMA_IDESC ((1u<<4)|(2u<<7)|(2u<<10)|((CH/8u)<<17)|((MTILE/16u)<<24))
#define DESC_BASE ((2ull<<61)|(1ull<<46)|(64ull<<32)|(1ull<<16))

#if defined(__CUDA_ARCH__) && (defined(__CUDA_ARCH_FEAT_SM103_ALL) || defined(__CUDA_ARCH_FEAT_SM100_ALL) || defined(__CUDA_ARCH_FEAT_SM101_ALL))
#define HAS_TC 1
#else
#define HAS_TC 0
#endif

__device__ __align__(1024) unsigned g_cbhi[TOTCH*8192];
__device__ float  g_sqc[NCB*KCB];
__device__ double g_loss;

__device__ __forceinline__ unsigned sptr(const void* p){
    unsigned r; asm("{ .reg .u64 t; cvta.to.shared.u64 t, %1; cvt.u32.u64 %0, t; }":"=r"(r):"l"(p)); return r;
}
__device__ __forceinline__ unsigned to_tf32(float v){
    unsigned r; asm("cvt.rna.tf32.f32 %0, %1;":"=r"(r):"f"(v)); return r;
}
#if HAS_TC
__device__ __forceinline__ void mbar_init(unsigned b,unsigned c){
    asm volatile("mbarrier.init.shared.b64 [%0], %1;"::"r"(b),"r"(c):"memory");
}
__device__ __forceinline__ void mbar_expect_tx(unsigned b,unsigned n){
    asm volatile("mbarrier.arrive.expect_tx.shared.b64 _, [%0], %1;"::"r"(b),"r"(n):"memory");
}
__device__ __forceinline__ void mbar_wait(unsigned b,unsigned p){
    for (int it=0; it<16384; it++){
        unsigned done;
        asm volatile("{\n\t.reg .pred P;\n\t"
            "mbarrier.try_wait.parity.acquire.cta.shared::cta.b64 P, [%1], %2, 0x989680;\n\t"
            "selp.b32 %0, 1, 0, P;\n\t}"
            : "=r"(done) : "r"(b), "r"(p) : "memory");
        if (done) return;
    }
}
__device__ __forceinline__ void bulk_g2s(unsigned dst,const void* src,unsigned n,unsigned bar){
    asm volatile("cp.async.bulk.shared::cluster.global.mbarrier::complete_tx::bytes [%0], [%1], %2, [%3];"
        ::"r"(dst),"l"(src),"r"(n),"r"(bar):"memory");
}
__device__ __forceinline__ void mma_tf32(unsigned d,unsigned a,unsigned long long bd,unsigned en){
    asm volatile("{\n\t.reg .pred p;\n\tsetp.ne.u32 p, %4, 0;\n\t"
        "tcgen05.mma.cta_group::1.kind::tf32 [%0], [%1], %2, %3, {%5,%5,%5,%5}, p;\n\t}"
        ::"r"(d),"r"(a),"l"(bd),"r"(MMA_IDESC),"r"(en),"r"(0u):"memory");
}
__device__ __forceinline__ void tc_commit(unsigned b){
    asm volatile("tcgen05.commit.cta_group::1.mbarrier::arrive::one.shared::cluster.b64 [%0];"::"r"(b):"memory");
}
__device__ __forceinline__ void fence_b(){ asm volatile("tcgen05.fence::before_thread_sync;":::"memory"); }
__device__ __forceinline__ void fence_a(){ asm volatile("tcgen05.fence::after_thread_sync;":::"memory"); }
__device__ __forceinline__ void tc_wait_st(){ asm volatile("tcgen05.wait::st.sync.aligned;":::"memory"); }
__device__ __forceinline__ void tc_wait_ld(){ asm volatile("tcgen05.wait::ld.sync.aligned;":::"memory"); }

#define STTM_X32(addr, r) \
    asm volatile("tcgen05.st.sync.aligned.32x32b.x32.b32 [%0], " \
        "{%1,%2,%3,%4,%5,%6,%7,%8,%9,%10,%11,%12,%13,%14,%15,%16," \
        "%17,%18,%19,%20,%21,%22,%23,%24,%25,%26,%27,%28,%29,%30,%31,%32};" \
        :: "r"(addr), \
        "r"((r)[0]),"r"((r)[1]),"r"((r)[2]),"r"((r)[3]),"r"((r)[4]),"r"((r)[5]),"r"((r)[6]),"r"((r)[7]), \
        "r"((r)[8]),"r"((r)[9]),"r"((r)[10]),"r"((r)[11]),"r"((r)[12]),"r"((r)[13]),"r"((r)[14]),"r"((r)[15]), \
        "r"((r)[16]),"r"((r)[17]),"r"((r)[18]),"r"((r)[19]),"r"((r)[20]),"r"((r)[21]),"r"((r)[22]),"r"((r)[23]), \
        "r"((r)[24]),"r"((r)[25]),"r"((r)[26]),"r"((r)[27]),"r"((r)[28]),"r"((r)[29]),"r"((r)[30]),"r"((r)[31]) \
        : "memory")
#define LDTM_X32(r, addr) \
    asm volatile("tcgen05.ld.sync.aligned.32x32b.x32.b32 " \
        "{%0,%1,%2,%3,%4,%5,%6,%7,%8,%9,%10,%11,%12,%13,%14,%15," \
        "%16,%17,%18,%19,%20,%21,%22,%23,%24,%25,%26,%27,%28,%29,%30,%31}, [%32];" \
        : "=r"((r)[0]),"=r"((r)[1]),"=r"((r)[2]),"=r"((r)[3]),"=r"((r)[4]),"=r"((r)[5]),"=r"((r)[6]),"=r"((r)[7]), \
        "=r"((r)[8]),"=r"((r)[9]),"=r"((r)[10]),"=r"((r)[11]),"=r"((r)[12]),"=r"((r)[13]),"=r"((r)[14]),"=r"((r)[15]), \
        "=r"((r)[16]),"=r"((r)[17]),"=r"((r)[18]),"=r"((r)[19]),"=r"((r)[20]),"=r"((r)[21]),"=r"((r)[22]),"=r"((r)[23]), \
        "=r"((r)[24]),"=r"((r)[25]),"=r"((r)[26]),"=r"((r)[27]),"=r"((r)[28]),"=r"((r)[29]),"=r"((r)[30]),"=r"((r)[31]) \
        : "r"(addr))

// lexicographic (value,index) less-than
__device__ __forceinline__ bool vkless(float va,int ka,float vb,int kb){
    return va < vb || (va == vb && ka < kb);
}
// merge candidate pair (c1,d1)<=(c2,d2) into running top-2 (a1,b1),(a2,b2)
__device__ __forceinline__ void merge2(float&a1,int&b1,float&a2,int&b2,
                                       float c1,int d1,float c2,int d2){
    if (vkless(c1,d1,a1,b1)){
        if (vkless(a1,b1,c2,d2)){ a2=a1; b2=b1; } else { a2=c2; b2=d2; }
        a1=c1; b1=d1;
    } else {
        if (vkless(c1,d1,a2,b2)){ a2=c1; b2=d1; }
    }
}
#endif // HAS_TC

// ---------------- prep ----------------
__global__ void rvq_prep_split(const float* __restrict__ cbs){
    unsigned idx = blockIdx.x*256u + threadIdx.x;
    if (idx == 0) g_loss = 0.0;
    float v = __ldg(cbs + idx);
    unsigned hi = to_tf32(v);
    unsigned k = (idx>>7)&1023, d = idx&127, cb = idx>>17;
    unsigned tile = cb*NCHUNK + (k>>6), nl = k&63;
    unsigned byte = ((nl>>3) + (d>>5)*8u)*1024u + (nl&7u)*128u + (d&31u)*4u;
    unsigned sw = byte ^ ((byte>>3)&0x70u);
    g_cbhi[tile*8192u + (sw>>2)] = hi;
}
__global__ void rvq_prep_sqc(const float* __restrict__ cbs){
    int code = blockIdx.x*256 + threadIdx.x;
    const float4* p = reinterpret_cast<const float4*>(cbs + (size_t)code*DIM);
    float part[2];
    #pragma unroll
    for (int hh=0; hh<2; hh++){
        float sq = 0.f;
        #pragma unroll
        for (int i=0;i<16;i++){
            float4 v = __ldg(p + hh + 2*i);
            sq=__fmaf_rn(v.x,v.x,sq); sq=__fmaf_rn(v.y,v.y,sq);
            sq=__fmaf_rn(v.z,v.z,sq); sq=__fmaf_rn(v.w,v.w,sq);
        }
        part[hh]=sq;
    }
    g_sqc[code] = __fadd_rn(part[0], part[1]);
}
__global__ void rvq_dummy(){}
__global__ void rvq_finish_kernel(float* lo){
    *lo = (float)(g_loss * (1.0/((double)Q_ELEMS*(double)NCB)));
}

// =================== tcgen05 main kernel (R8 base + sqc-preload + ILP trackers) ===================
struct SmemTC {
    unsigned char B[3][32768];      // 96 KB TMA ring, 1024-aligned
    float  R[MTILE][RSTR];          // 67.6 KB residual rows
    float  sqc_cb[KCB];             // 4 KB: whole codebook's ||w||^2
    int    codes_sm[NCB][MTILE];
    double lred[NTHR];
    unsigned long long mbar[7];     // bfull[3], cbar[4]
    unsigned tmem_ptr;
};

__global__ __launch_bounds__(NTHR,1)
void rvq_tc_kernel(const float* __restrict__ emb, const float* __restrict__ cbs,
                   float* __restrict__ codes_f, int* __restrict__ codes_i,
                   float* __restrict__ qout, int do_loss){
#if HAS_TC
    extern __shared__ char raw[];
    uintptr_t base = ((uintptr_t)raw + 1023u) & ~(uintptr_t)1023u;
    SmemTC& s = *reinterpret_cast<SmemTC*>(base);
    const int tid = threadIdx.x, wid = tid>>5;
    const int row = blockIdx.x*MTILE + tid;
    const unsigned sB = sptr(&s.B[0][0]);
    unsigned bfull[3], cbar[4];
    #pragma unroll
    for (int i=0;i<3;i++) bfull[i]=sptr(&s.mbar[i]);
    #pragma unroll
    for (int i=0;i<4;i++) cbar[i]=sptr(&s.mbar[3+i]);

    if (wid == 0)
        asm volatile("tcgen05.alloc.cta_group::1.sync.aligned.shared::cta.b32 [%0], %1;"
                     ::"r"(sptr(&s.tmem_ptr)),"r"(512):"memory");
    if (tid == 0){
        #pragma unroll
        for (int i=0;i<7;i++) mbar_init(sptr(&s.mbar[i]),1);
    }
    __syncthreads();
    unsigned tmem;
    asm volatile("ld.shared.b32 %0, [%1];":"=r"(tmem):"r"(sptr(&s.tmem_ptr)));

    // prefetch chunks 0,1
    if (tid == 0){
        mbar_expect_tx(bfull[0], 32768u);
        bulk_g2s(sB,          g_cbhi,         32768u, bfull[0]);
        mbar_expect_tx(bfull[1], 32768u);
        bulk_g2s(sB + 32768u, g_cbhi + 8192u, 32768u, bfull[1]);
    }

    // load 128 embedding rows into smem (coalesced)
    {
        const float4* ep = reinterpret_cast<const float4*>(emb + (size_t)(blockIdx.x*MTILE)*DIM);
        for (int idx = tid; idx < MTILE*32; idx += NTHR)
            *reinterpret_cast<float4*>(&s.R[idx>>5][(idx&31)*4]) = __ldg(ep + idx);
    }
    __syncthreads();

    double lacc = 0.0;

    for (int cb = 0; cb < NCB; cb++){
        // ---- preload this codebook's sqc into smem (coalesced, once)
        #pragma unroll
        for (int q=0;q<KCB/NTHR;q++)
            s.sqc_cb[tid + NTHR*q] = __ldg(&g_sqc[cb*KCB + tid + NTHR*q]);

        // ---- A norm + tf32-hi -> TMEM (128 cols at TM_A)
        float Acur;
        {
            float p4[4];
            #pragma unroll
            for (int b=0;b<4;b++){
                unsigned hi[32];
                float p = 0.f;
                #pragma unroll
                for (int q=0;q<8;q++){
                    float4 v4 = *reinterpret_cast<const float4*>(&s.R[tid][b*32+q*4]);
                    p = __fmaf_rn(v4.x,v4.x,p); hi[q*4+0]=to_tf32(v4.x);
                    p = __fmaf_rn(v4.y,v4.y,p); hi[q*4+1]=to_tf32(v4.y);
                    p = __fmaf_rn(v4.z,v4.z,p); hi[q*4+2]=to_tf32(v4.z);
                    p = __fmaf_rn(v4.w,v4.w,p); hi[q*4+3]=to_tf32(v4.w);
                }
                p4[b]=p;
                STTM_X32(tmem+TM_A+b*32+((unsigned)wid<<21), hi);
            }
            Acur = __fadd_rn(__fadd_rn(__fadd_rn(p4[0],p4[1]),p4[2]),p4[3]);
            tc_wait_st(); fence_b();
        }

        float pv1 = FLT_MAX, pv2 = FLT_MAX;   // persistent top-2 for this codebook
        int   pk1 = 0,       pk2 = 0;

        for (int i=0;i<NCHUNK+2;i++){
            __syncthreads();
            if (tid == 0 && i < NCHUNK){
                int g = cb*NCHUNK + i;
                fence_a();
                mbar_wait(bfull[g%3], (g/3)&1);
                unsigned long long bd = DESC_BASE |
                    (((unsigned long long)(sB + (unsigned)(g%3)*32768u)>>4)&0x3FFFull);
                unsigned dt = tmem + (g&3)*64;
                #pragma unroll
                for (int ks=0; ks<16; ks++)
                    mma_tf32(dt, tmem+TM_A+ks*8, bd + (ks>>2)*512 + (ks&3)*2, ks?1u:0u);
                tc_commit(cbar[g&3]);
                int f = g + 2;
                if (f < TOTCH){
                    if (g >= 1) mbar_wait(cbar[(g-1)&3], ((g-1)>>2)&1);
                    mbar_expect_tx(bfull[f%3], 32768u);
                    bulk_g2s(sB + (unsigned)(f%3)*32768u, g_cbhi+(size_t)f*8192u,
                             32768u, bfull[f%3]);
                }
            }
            if (i >= 2){
                int e = cb*NCHUNK + i - 2;
                mbar_wait(cbar[e&3], (e>>2)&1);
                fence_a();
                const int kb = (i-2)*CH;
                unsigned dt = tmem + (e&3)*64;
                unsigned dr0[32], dr1[32];
                LDTM_X32(dr0, dt);
                LDTM_X32(dr1, dt + 32);
                tc_wait_ld();

                // 4 chunk-local trackers, ascending k within each tracker
                float tv1[4], tv2[4]; int tk1[4], tk2[4];
                #pragma unroll
                for (int t=0;t<4;t++){ tv1[t]=FLT_MAX; tv2[t]=FLT_MAX; tk1[t]=0; tk2[t]=0; }
                const float* sq = &s.sqc_cb[kb];
                #pragma unroll
                for (int q=0;q<8;q++){
                    #pragma unroll
                    for (int t=0;t<4;t++){
                        int c = q*4 + t;
                        float sv = __fmaf_rn(-2.f, __uint_as_float(dr0[c]), sq[c]);
                        if (sv < tv1[t]){ tv2[t]=tv1[t]; tk2[t]=tk1[t]; tv1[t]=sv; tk1[t]=kb+c; }
                        else if (sv < tv2[t]){ tv2[t]=sv; tk2[t]=kb+c; }
                    }
                }
                #pragma unroll
                for (int q=0;q<8;q++){
                    #pragma unroll
                    for (int t=0;t<4;t++){
                        int c = q*4 + t;
                        float sv = __fmaf_rn(-2.f, __uint_as_float(dr1[c]), sq[32+c]);
                        if (sv < tv1[t]){ tv2[t]=tv1[t]; tk2[t]=tk1[t]; tv1[t]=sv; tk1[t]=kb+32+c; }
                        else if (sv < tv2[t]){ tv2[t]=sv; tk2[t]=kb+32+c; }
                    }
                }
                // fold into persistent top-2 (lexicographic; order-independent)
                #pragma unroll
                for (int t=0;t<4;t++)
                    merge2(pv1,pk1,pv2,pk2, tv1[t],tk1[t], tv2[t],tk2[t]);
                fence_b();
            }
        }

        // ---- exact recheck of top-2 (round-1 arithmetic)
        const float* cbbase = cbs + (size_t)cb*KCB*DIM;
        int best;
        {
            float da, db;
            {
                const float4* wp = reinterpret_cast<const float4*>(cbbase + (size_t)pk1*DIM);
                float acc = 0.f;
                #pragma unroll
                for (int i=0;i<32;i++){
                    float4 w = __ldg(wp+i);
                    const float4 r4 = *reinterpret_cast<const float4*>(&s.R[tid][4*i]);
                    acc=__fmaf_rn(r4.x,w.x,acc); acc=__fmaf_rn(r4.y,w.y,acc);
                    acc=__fmaf_rn(r4.z,w.z,acc); acc=__fmaf_rn(r4.w,w.w,acc);
                }
                da = __fadd_rn(__fmaf_rn(-2.f,acc,Acur), s.sqc_cb[pk1]);
            }
            {
                const float4* wp = reinterpret_cast<const float4*>(cbbase + (size_t)pk2*DIM);
                float acc = 0.f;
                #pragma unroll
                for (int i=0;i<32;i++){
                    float4 w = __ldg(wp+i);
                    const float4 r4 = *reinterpret_cast<const float4*>(&s.R[tid][4*i]);
                    acc=__fmaf_rn(r4.x,w.x,acc); acc=__fmaf_rn(r4.y,w.y,acc);
                    acc=__fmaf_rn(r4.z,w.z,acc); acc=__fmaf_rn(r4.w,w.w,acc);
                }
                db = __fadd_rn(__fmaf_rn(-2.f,acc,Acur), s.sqc_cb[pk2]);
            }
            best = (db < da || (db == da && pk2 < pk1)) ? pk2 : pk1;
        }
        s.codes_sm[cb][tid] = best;

        { // residual update + loss
            const float4* wp = reinterpret_cast<const float4*>(cbbase + (size_t)best*DIM);
            #pragma unroll
            for (int i=0;i<32;i++){
                float4 w = __ldg(wp+i);
                float4 r4 = *reinterpret_cast<const float4*>(&s.R[tid][4*i]);
                float r0=__fadd_rn(r4.x,-w.x), r1=__fadd_rn(r4.y,-w.y);
                float r2=__fadd_rn(r4.z,-w.z), r3=__fadd_rn(r4.w,-w.w);
                float4 o; o.x=r0; o.y=r1; o.z=r2; o.w=r3;
                *reinterpret_cast<float4*>(&s.R[tid][4*i]) = o;
                lacc += (double)(r0*r0)+(double)(r1*r1)+(double)(r2*r2)+(double)(r3*r3);
            }
        }
        __syncthreads();
    }

    // ---- outputs
    if (codes_f){
        #pragma unroll
        for (int c=0;c<NCB;c++) codes_f[(size_t)row*NCB+c] = (float)s.codes_sm[c][tid];
    }
    if (codes_i){
        #pragma unroll
        for (int c=0;c<NCB;c++) codes_i[(size_t)row*NCB+c] = s.codes_sm[c][tid];
    }
    if (qout){
        const float4* ep = reinterpret_cast<const float4*>(emb + (size_t)row*DIM);
        #pragma unroll
        for (int i=0;i<32;i++){
            float4 e = __ldg(ep+i);
            float4 r4 = *reinterpret_cast<const float4*>(&s.R[tid][4*i]);
            float4 o;
            o.x=__fadd_rn(e.x,-r4.x); o.y=__fadd_rn(e.y,-r4.y);
            o.z=__fadd_rn(e.z,-r4.z); o.w=__fadd_rn(e.w,-r4.w);
            *reinterpret_cast<float4*>(qout + (size_t)row*DIM + 4*i) = o;
        }
    }
    if (do_loss){
        s.lred[tid] = lacc;
        __syncthreads();
        #pragma unroll
        for (int off=NTHR/2; off>=1; off>>=1){
            if (tid<off) s.lred[tid]+=s.lred[tid+off];
            __syncthreads();
        }
        if (tid==0) atomicAdd(&g_loss, s.lred[0]);
    }
    __syncthreads();
    if (wid == 0){
        asm volatile("tcgen05.relinquish_alloc_permit.cta_group::1.sync.aligned;");
        asm volatile("tcgen05.dealloc.cta_group::1.sync.aligned.b32 %0, %1;"::"r"(tmem),"r"(512));
    }
#endif // HAS_TC
}

extern "C" void kernel_launch(void* const* d_in, const int* in_sizes, int n_in,
                              void* d_out, int out_size){
    const float* emb = (const float*)d_in[0];
    const float* cbs = (const float*)d_in[1];
    if (n_in >= 2 && in_sizes[0] == NCB*KCB*DIM && in_sizes[1] == NROWS*DIM){
        const float* t=emb; emb=cbs; cbs=t;
    }
    float* out=(float*)d_out;
    float *codes_f=nullptr,*qout=nullptr,*lossp=nullptr; int* codes_i=nullptr;
    if (out_size >= CODES_ELEMS+Q_ELEMS+1){
        codes_f=out; qout=out+CODES_ELEMS; lossp=out+CODES_ELEMS+Q_ELEMS;
    } else if (out_size == Q_ELEMS) qout=out;
    else if (out_size == CODES_ELEMS) codes_i=(int*)d_out;
    else codes_f=out;

    cudaFuncSetAttribute(rvq_tc_kernel,
        cudaFuncAttributeMaxDynamicSharedMemorySize, (int)(sizeof(SmemTC)+1024));

    rvq_prep_split<<<NCB*KCB*DIM/256, 256>>>(cbs);       // launch 0
    rvq_prep_sqc<<<NCB*KCB/256, 256>>>(cbs);             // launch 1
    rvq_dummy<<<1,1>>>();                                 // launch 2 (tc at pos 3 for ncu)
    rvq_tc_kernel<<<NCTA, NTHR, sizeof(SmemTC)+1024>>>(  // launch 3
        emb, cbs, codes_f, codes_i, qout, lossp!=nullptr);
    rvq_finish_kernel<<<1,1>>>(lossp ? lossp : (float*)d_out); // launch 4
}

// round 12
// speedup vs baseline: 3.4306x; 3.4306x over previous
#include <cuda_runtime.h>
#include <cfloat>
#include <cstdint>

#define NCB 8
#define KCB 1024
#define DIM 128
#define NROWS 32768
#define MTILE 128
#define NCTA (NROWS/MTILE)     // 256
#define NTHR 128
#define CH 64
#define NCHUNK 16
#define TOTCH (NCB*NCHUNK)      // 128
#define RSTR (DIM+4)

#define CODES_ELEMS (NROWS*NCB)
#define Q_ELEMS     (NROWS*DIM)

#define TM_A 256                 // A: cols 256..383 ; D ring: 4 x 64 cols at 0,64,128,192

#define MMA_IDESC ((1u<<4)|(2u<<7)|(2u<<10)|((CH/8u)<<17)|((MTILE/16u)<<24))
#define DESC_BASE ((2ull<<61)|(1ull<<46)|(64ull<<32)|(1ull<<16))

#if defined(__CUDA_ARCH__) && (defined(__CUDA_ARCH_FEAT_SM103_ALL) || defined(__CUDA_ARCH_FEAT_SM100_ALL) || defined(__CUDA_ARCH_FEAT_SM101_ALL))
#define HAS_TC 1
#else
#define HAS_TC 0
#endif

__device__ __align__(1024) unsigned g_cbhi[TOTCH*8192];
__device__ float  g_sqc[NCB*KCB];
__device__ double g_loss;

__device__ __forceinline__ unsigned sptr(const void* p){
    unsigned r; asm("{ .reg .u64 t; cvta.to.shared.u64 t, %1; cvt.u32.u64 %0, t; }":"=r"(r):"l"(p)); return r;
}
__device__ __forceinline__ unsigned to_tf32(float v){
    unsigned r; asm("cvt.rna.tf32.f32 %0, %1;":"=r"(r):"f"(v)); return r;
}
#if HAS_TC
__device__ __forceinline__ void mbar_init(unsigned b,unsigned c){
    asm volatile("mbarrier.init.shared.b64 [%0], %1;"::"r"(b),"r"(c):"memory");
}
__device__ __forceinline__ void mbar_expect_tx(unsigned b,unsigned n){
    asm volatile("mbarrier.arrive.expect_tx.shared.b64 _, [%0], %1;"::"r"(b),"r"(n):"memory");
}
__device__ __forceinline__ void mbar_wait(unsigned b,unsigned p){
    for (int it=0; it<16384; it++){
        unsigned done;
        asm volatile("{\n\t.reg .pred P;\n\t"
            "mbarrier.try_wait.parity.acquire.cta.shared::cta.b64 P, [%1], %2, 0x989680;\n\t"
            "selp.b32 %0, 1, 0, P;\n\t}"
            : "=r"(done) : "r"(b), "r"(p) : "memory");
        if (done) return;
    }
}
__device__ __forceinline__ void bulk_g2s(unsigned dst,const void* src,unsigned n,unsigned bar){
    asm volatile("cp.async.bulk.shared::cluster.global.mbarrier::complete_tx::bytes [%0], [%1], %2, [%3];"
        ::"r"(dst),"l"(src),"r"(n),"r"(bar):"memory");
}
__device__ __forceinline__ void mma_tf32(unsigned d,unsigned a,unsigned long long bd,unsigned en){
    asm volatile("{\n\t.reg .pred p;\n\tsetp.ne.u32 p, %4, 0;\n\t"
        "tcgen05.mma.cta_group::1.kind::tf32 [%0], [%1], %2, %3, {%5,%5,%5,%5}, p;\n\t}"
        ::"r"(d),"r"(a),"l"(bd),"r"(MMA_IDESC),"r"(en),"r"(0u):"memory");
}
__device__ __forceinline__ void tc_commit(unsigned b){
    asm volatile("tcgen05.commit.cta_group::1.mbarrier::arrive::one.shared::cluster.b64 [%0];"::"r"(b):"memory");
}
__device__ __forceinline__ void fence_b(){ asm volatile("tcgen05.fence::before_thread_sync;":::"memory"); }
__device__ __forceinline__ void fence_a(){ asm volatile("tcgen05.fence::after_thread_sync;":::"memory"); }
__device__ __forceinline__ void tc_wait_st(){ asm volatile("tcgen05.wait::st.sync.aligned;":::"memory"); }
__device__ __forceinline__ void tc_wait_ld(){ asm volatile("tcgen05.wait::ld.sync.aligned;":::"memory"); }

#define STTM_X32(addr, r) \
    asm volatile("tcgen05.st.sync.aligned.32x32b.x32.b32 [%0], " \
        "{%1,%2,%3,%4,%5,%6,%7,%8,%9,%10,%11,%12,%13,%14,%15,%16," \
        "%17,%18,%19,%20,%21,%22,%23,%24,%25,%26,%27,%28,%29,%30,%31,%32};" \
        :: "r"(addr), \
        "r"((r)[0]),"r"((r)[1]),"r"((r)[2]),"r"((r)[3]),"r"((r)[4]),"r"((r)[5]),"r"((r)[6]),"r"((r)[7]), \
        "r"((r)[8]),"r"((r)[9]),"r"((r)[10]),"r"((r)[11]),"r"((r)[12]),"r"((r)[13]),"r"((r)[14]),"r"((r)[15]), \
        "r"((r)[16]),"r"((r)[17]),"r"((r)[18]),"r"((r)[19]),"r"((r)[20]),"r"((r)[21]),"r"((r)[22]),"r"((r)[23]), \
        "r"((r)[24]),"r"((r)[25]),"r"((r)[26]),"r"((r)[27]),"r"((r)[28]),"r"((r)[29]),"r"((r)[30]),"r"((r)[31]) \
        : "memory")
#define LDTM_X32(r, addr) \
    asm volatile("tcgen05.ld.sync.aligned.32x32b.x32.b32 " \
        "{%0,%1,%2,%3,%4,%5,%6,%7,%8,%9,%10,%11,%12,%13,%14,%15," \
        "%16,%17,%18,%19,%20,%21,%22,%23,%24,%25,%26,%27,%28,%29,%30,%31}, [%32];" \
        : "=r"((r)[0]),"=r"((r)[1]),"=r"((r)[2]),"=r"((r)[3]),"=r"((r)[4]),"=r"((r)[5]),"=r"((r)[6]),"=r"((r)[7]), \
        "=r"((r)[8]),"=r"((r)[9]),"=r"((r)[10]),"=r"((r)[11]),"=r"((r)[12]),"=r"((r)[13]),"=r"((r)[14]),"=r"((r)[15]), \
        "=r"((r)[16]),"=r"((r)[17]),"=r"((r)[18]),"=r"((r)[19]),"=r"((r)[20]),"=r"((r)[21]),"=r"((r)[22]),"=r"((r)[23]), \
        "=r"((r)[24]),"=r"((r)[25]),"=r"((r)[26]),"=r"((r)[27]),"=r"((r)[28]),"=r"((r)[29]),"=r"((r)[30]),"=r"((r)[31]) \
        : "r"(addr))
#endif // HAS_TC

// ---------------- prep ----------------
__global__ void rvq_prep_split(const float* __restrict__ cbs){
    unsigned idx = blockIdx.x*256u + threadIdx.x;
    if (idx == 0) g_loss = 0.0;
    float v = __ldg(cbs + idx);
    unsigned hi = to_tf32(v);
    unsigned k = (idx>>7)&1023, d = idx&127, cb = idx>>17;
    unsigned tile = cb*NCHUNK + (k>>6), nl = k&63;
    unsigned byte = ((nl>>3) + (d>>5)*8u)*1024u + (nl&7u)*128u + (d&31u)*4u;
    unsigned sw = byte ^ ((byte>>3)&0x70u);
    g_cbhi[tile*8192u + (sw>>2)] = hi;
}
__global__ void rvq_prep_sqc(const float* __restrict__ cbs){
    int code = blockIdx.x*256 + threadIdx.x;
    const float4* p = reinterpret_cast<const float4*>(cbs + (size_t)code*DIM);
    float part[2];
    #pragma unroll
    for (int hh=0; hh<2; hh++){
        float sq = 0.f;
        #pragma unroll
        for (int i=0;i<16;i++){
            float4 v = __ldg(p + hh + 2*i);
            sq=__fmaf_rn(v.x,v.x,sq); sq=__fmaf_rn(v.y,v.y,sq);
            sq=__fmaf_rn(v.z,v.z,sq); sq=__fmaf_rn(v.w,v.w,sq);
        }
        part[hh]=sq;
    }
    g_sqc[code] = __fadd_rn(part[0], part[1]);
}
__global__ void rvq_dummy(){}
__global__ void rvq_finish_kernel(float* lo){
    *lo = (float)(g_loss * (1.0/((double)Q_ELEMS*(double)NCB)));
}

// =================== tcgen05 main kernel (R8 + 4-slot B ring + sqct prefetch) ===================
struct SmemTC {
    unsigned char B[4][32768];      // 128 KB TMA ring, 1024-aligned
    float  R[MTILE][RSTR];          // 67.6 KB residual rows
    float  sqct[CH];
    int    codes_sm[NCB][MTILE];
    double lred[NTHR];
    unsigned long long mbar[8];     // bfull[4], cbar[4]
    unsigned tmem_ptr;
};

__global__ __launch_bounds__(NTHR,1)
void rvq_tc_kernel(const float* __restrict__ emb, const float* __restrict__ cbs,
                   float* __restrict__ codes_f, int* __restrict__ codes_i,
                   float* __restrict__ qout, int do_loss){
#if HAS_TC
    extern __shared__ char raw[];
    uintptr_t base = ((uintptr_t)raw + 1023u) & ~(uintptr_t)1023u;
    SmemTC& s = *reinterpret_cast<SmemTC*>(base);
    const int tid = threadIdx.x, wid = tid>>5;
    const int row = blockIdx.x*MTILE + tid;
    const unsigned sB = sptr(&s.B[0][0]);
    unsigned bfull[4], cbar[4];
    #pragma unroll
    for (int i=0;i<4;i++) bfull[i]=sptr(&s.mbar[i]);
    #pragma unroll
    for (int i=0;i<4;i++) cbar[i]=sptr(&s.mbar[4+i]);

    if (wid == 0)
        asm volatile("tcgen05.alloc.cta_group::1.sync.aligned.shared::cta.b32 [%0], %1;"
                     ::"r"(sptr(&s.tmem_ptr)),"r"(512):"memory");
    if (tid == 0){
        #pragma unroll
        for (int i=0;i<8;i++) mbar_init(sptr(&s.mbar[i]),1);
    }
    __syncthreads();
    unsigned tmem;
    asm volatile("ld.shared.b32 %0, [%1];":"=r"(tmem):"r"(sptr(&s.tmem_ptr)));

    // prefetch chunks 0,1 into slots 0,1
    if (tid == 0){
        mbar_expect_tx(bfull[0], 32768u);
        bulk_g2s(sB,          g_cbhi,         32768u, bfull[0]);
        mbar_expect_tx(bfull[1], 32768u);
        bulk_g2s(sB + 32768u, g_cbhi + 8192u, 32768u, bfull[1]);
    }

    // load 128 embedding rows into smem (coalesced)
    {
        const float4* ep = reinterpret_cast<const float4*>(emb + (size_t)(blockIdx.x*MTILE)*DIM);
        for (int idx = tid; idx < MTILE*32; idx += NTHR)
            *reinterpret_cast<float4*>(&s.R[idx>>5][(idx&31)*4]) = __ldg(ep + idx);
    }
    __syncthreads();

    double lacc = 0.0;

    for (int cb = 0; cb < NCB; cb++){
        // ---- A norm + tf32-hi -> TMEM (128 cols at TM_A)
        float Acur;
        {
            float p4[4];
            #pragma unroll
            for (int b=0;b<4;b++){
                unsigned hi[32];
                float p = 0.f;
                #pragma unroll
                for (int q=0;q<8;q++){
                    float4 v4 = *reinterpret_cast<const float4*>(&s.R[tid][b*32+q*4]);
                    p = __fmaf_rn(v4.x,v4.x,p); hi[q*4+0]=to_tf32(v4.x);
                    p = __fmaf_rn(v4.y,v4.y,p); hi[q*4+1]=to_tf32(v4.y);
                    p = __fmaf_rn(v4.z,v4.z,p); hi[q*4+2]=to_tf32(v4.z);
                    p = __fmaf_rn(v4.w,v4.w,p); hi[q*4+3]=to_tf32(v4.w);
                }
                p4[b]=p;
                STTM_X32(tmem+TM_A+b*32+((unsigned)wid<<21), hi);
            }
            Acur = __fadd_rn(__fadd_rn(__fadd_rn(p4[0],p4[1]),p4[2]),p4[3]);
            tc_wait_st(); fence_b();
        }

        float v1 = FLT_MAX, v2 = FLT_MAX;
        int   k1 = 0,       k2 = 0;

        for (int i=0;i<NCHUNK+2;i++){
            __syncthreads();
            if (tid == 0 && i < NCHUNK){
                int g = cb*NCHUNK + i;
                fence_a();
                mbar_wait(bfull[g&3], (g>>2)&1);
                unsigned long long bd = DESC_BASE |
                    (((unsigned long long)(sB + (unsigned)(g&3)*32768u)>>4)&0x3FFFull);
                unsigned dt = tmem + (g&3)*64;
                #pragma unroll
                for (int ks=0; ks<16; ks++)
                    mma_tf32(dt, tmem+TM_A+ks*8, bd + (ks>>2)*512 + (ks&3)*2, ks?1u:0u);
                tc_commit(cbar[g&3]);
                int f = g + 2;
                if (f < TOTCH){
                    // slot f&3 last read by MMA chunk f-4 (epilogued already) -> fast wait
                    if (f >= 4) mbar_wait(cbar[f&3], ((f-4)>>2)&1);
                    mbar_expect_tx(bfull[f&3], 32768u);
                    bulk_g2s(sB + (unsigned)(f&3)*32768u, g_cbhi+(size_t)f*8192u,
                             32768u, bfull[f&3]);
                }
            }
            if (i >= 2){
                int e = cb*NCHUNK + i - 2;
                // prefetch sqct BEFORE the wait so LDG latency hides under it
                float sqv = 0.f;
                if (tid < CH) sqv = __ldg(&g_sqc[cb*KCB + (i-2)*CH + tid]);
                mbar_wait(cbar[e&3], (e>>2)&1);
                fence_a();
                if (tid < CH) s.sqct[tid] = sqv;
                __syncthreads();
                int kb = (i-2)*CH;
                unsigned dt = tmem + (e&3)*64;
                unsigned dr0[32], dr1[32];
                LDTM_X32(dr0, dt);
                LDTM_X32(dr1, dt + 32);
                tc_wait_ld();
                #pragma unroll
                for (int j=0;j<32;j++){
                    float sv = __fmaf_rn(-2.f, __uint_as_float(dr0[j]), s.sqct[j]);
                    int kg = kb + j;
                    if (sv < v1){ v2=v1; k2=k1; v1=sv; k1=kg; }
                    else if (sv < v2){ v2=sv; k2=kg; }
                }
                #pragma unroll
                for (int j=0;j<32;j++){
                    float sv = __fmaf_rn(-2.f, __uint_as_float(dr1[j]), s.sqct[32+j]);
                    int kg = kb + 32 + j;
                    if (sv < v1){ v2=v1; k2=k1; v1=sv; k1=kg; }
                    else if (sv < v2){ v2=sv; k2=kg; }
                }
                fence_b();
            }
        }

        // ---- exact recheck of top-2 (round-1 arithmetic)
        const float* cbbase = cbs + (size_t)cb*KCB*DIM;
        int best;
        {
            float da, db;
            {
                const float4* wp = reinterpret_cast<const float4*>(cbbase + (size_t)k1*DIM);
                float acc = 0.f;
                #pragma unroll
                for (int i=0;i<32;i++){
                    float4 w = __ldg(wp+i);
                    const float4 r4 = *reinterpret_cast<const float4*>(&s.R[tid][4*i]);
                    acc=__fmaf_rn(r4.x,w.x,acc); acc=__fmaf_rn(r4.y,w.y,acc);
                    acc=__fmaf_rn(r4.z,w.z,acc); acc=__fmaf_rn(r4.w,w.w,acc);
                }
                da = __fadd_rn(__fmaf_rn(-2.f,acc,Acur), __ldg(&g_sqc[cb*KCB+k1]));
            }
            {
                const float4* wp = reinterpret_cast<const float4*>(cbbase + (size_t)k2*DIM);
                float acc = 0.f;
                #pragma unroll
                for (int i=0;i<32;i++){
                    float4 w = __ldg(wp+i);
                    const float4 r4 = *reinterpret_cast<const float4*>(&s.R[tid][4*i]);
                    acc=__fmaf_rn(r4.x,w.x,acc); acc=__fmaf_rn(r4.y,w.y,acc);
                    acc=__fmaf_rn(r4.z,w.z,acc); acc=__fmaf_rn(r4.w,w.w,acc);
                }
                db = __fadd_rn(__fmaf_rn(-2.f,acc,Acur), __ldg(&g_sqc[cb*KCB+k2]));
            }
            best = (db < da || (db == da && k2 < k1)) ? k2 : k1;
        }
        s.codes_sm[cb][tid] = best;

        { // residual update + loss
            const float4* wp = reinterpret_cast<const float4*>(cbbase + (size_t)best*DIM);
            #pragma unroll
            for (int i=0;i<32;i++){
                float4 w = __ldg(wp+i);
                float4 r4 = *reinterpret_cast<const float4*>(&s.R[tid][4*i]);
                float r0=__fadd_rn(r4.x,-w.x), r1=__fadd_rn(r4.y,-w.y);
                float r2=__fadd_rn(r4.z,-w.z), r3=__fadd_rn(r4.w,-w.w);
                float4 o; o.x=r0; o.y=r1; o.z=r2; o.w=r3;
                *reinterpret_cast<float4*>(&s.R[tid][4*i]) = o;
                lacc += (double)(r0*r0)+(double)(r1*r1)+(double)(r2*r2)+(double)(r3*r3);
            }
        }
        __syncthreads();
    }

    // ---- outputs
    if (codes_f){
        #pragma unroll
        for (int c=0;c<NCB;c++) codes_f[(size_t)row*NCB+c] = (float)s.codes_sm[c][tid];
    }
    if (codes_i){
        #pragma unroll
        for (int c=0;c<NCB;c++) codes_i[(size_t)row*NCB+c] = s.codes_sm[c][tid];
    }
    if (qout){
        const float4* ep = reinterpret_cast<const float4*>(emb + (size_t)row*DIM);
        #pragma unroll
        for (int i=0;i<32;i++){
            float4 e = __ldg(ep+i);
            float4 r4 = *reinterpret_cast<const float4*>(&s.R[tid][4*i]);
            float4 o;
            o.x=__fadd_rn(e.x,-r4.x); o.y=__fadd_rn(e.y,-r4.y);
            o.z=__fadd_rn(e.z,-r4.z); o.w=__fadd_rn(e.w,-r4.w);
            *reinterpret_cast<float4*>(qout + (size_t)row*DIM + 4*i) = o;
        }
    }
    if (do_loss){
        s.lred[tid] = lacc;
        __syncthreads();
        #pragma unroll
        for (int off=NTHR/2; off>=1; off>>=1){
            if (tid<off) s.lred[tid]+=s.lred[tid+off];
            __syncthreads();
        }
        if (tid==0) atomicAdd(&g_loss, s.lred[0]);
    }
    __syncthreads();
    if (wid == 0){
        asm volatile("tcgen05.relinquish_alloc_permit.cta_group::1.sync.aligned;");
        asm volatile("tcgen05.dealloc.cta_group::1.sync.aligned.b32 %0, %1;"::"r"(tmem),"r"(512));
    }
#endif // HAS_TC
}

extern "C" void kernel_launch(void* const* d_in, const int* in_sizes, int n_in,
                              void* d_out, int out_size){
    const float* emb = (const float*)d_in[0];
    const float* cbs = (const float*)d_in[1];
    if (n_in >= 2 && in_sizes[0] == NCB*KCB*DIM && in_sizes[1] == NROWS*DIM){
        const float* t=emb; emb=cbs; cbs=t;
    }
    float* out=(float*)d_out;
    float *codes_f=nullptr,*qout=nullptr,*lossp=nullptr; int* codes_i=nullptr;
    if (out_size >= CODES_ELEMS+Q_ELEMS+1){
        codes_f=out; qout=out+CODES_ELEMS; lossp=out+CODES_ELEMS+Q_ELEMS;
    } else if (out_size == Q_ELEMS) qout=out;
    else if (out_size == CODES_ELEMS) codes_i=(int*)d_out;
    else codes_f=out;

    cudaFuncSetAttribute(rvq_tc_kernel,
        cudaFuncAttributeMaxDynamicSharedMemorySize, (int)(sizeof(SmemTC)+1024));

    rvq_prep_split<<<NCB*KCB*DIM/256, 256>>>(cbs);       // launch 0
    rvq_prep_sqc<<<NCB*KCB/256, 256>>>(cbs);             // launch 1
    rvq_dummy<<<1,1>>>();                                 // launch 2 (tc at pos 3 for ncu)
    rvq_tc_kernel<<<NCTA, NTHR, sizeof(SmemTC)+1024>>>(  // launch 3
        emb, cbs, codes_f, codes_i, qout, lossp!=nullptr);
    rvq_finish_kernel<<<1,1>>>(lossp ? lossp : (float*)d_out); // launch 4
}